// round 1
// baseline (speedup 1.0000x reference)
#include <cuda_runtime.h>
#include <cuda_bf16.h>
#include <stdint.h>

// Problem constants (shape-fixed dataset); runtime sizes are still read from
// in_sizes and used as loop bounds, these only size the static scratch.
#define MAX_N    4096
#define MAX_M    4096
#define MAX_B    128
#define MAX_NNZ  1638400

// __device__ global scratch (no allocations allowed)
__device__ uint32_t g_packed[MAX_NNZ];          // (col<<8) | (val+127)
__device__ int      g_rowptr[MAX_N + 1];
__device__ float    g_xT[MAX_M * MAX_B];        // xT[m*B + b], 2 MB -> L2 resident

// ---------------------------------------------------------------------------
// Kernel 1: pack (col, val) into one u32 per nnz
// ---------------------------------------------------------------------------
__global__ void pack_kernel(const int* __restrict__ wval,
                            const int* __restrict__ col,
                            int nnz)
{
    int k = blockIdx.x * blockDim.x + threadIdx.x;
    if (k < nnz) {
        uint32_t c = (uint32_t)col[k];
        uint32_t v = (uint32_t)(wval[k] + 127);   // [-127,127] -> [0,254]
        g_packed[k] = (c << 8) | (v & 0xFFu);
    }
}

// ---------------------------------------------------------------------------
// Kernel 2: rowptr via binary search on sorted row_ids
// ---------------------------------------------------------------------------
__global__ void rowptr_kernel(const int* __restrict__ row_ids, int nnz, int n)
{
    int r = blockIdx.x * blockDim.x + threadIdx.x;
    if (r <= n) {
        int lo = 0, hi = nnz;
        while (lo < hi) {
            int mid = (lo + hi) >> 1;
            if (row_ids[mid] < r) lo = mid + 1; else hi = mid;
        }
        g_rowptr[r] = lo;
    }
}

// ---------------------------------------------------------------------------
// Kernel 3: transpose x[B,M] -> xT[M,B] via smem tile
// ---------------------------------------------------------------------------
__global__ void transpose_kernel(const float* __restrict__ x, int Bsz, int M)
{
    __shared__ float tile[32][33];
    int m0 = blockIdx.x * 32;
    int b0 = blockIdx.y * 32;
    int tx = threadIdx.x, ty = threadIdx.y;

    int m = m0 + tx, b = b0 + ty;
    if (b < Bsz && m < M) tile[ty][tx] = x[b * M + m];
    __syncthreads();
    // write xT[m][b]: m = m0+ty, b = b0+tx (coalesced over tx)
    int mo = m0 + ty, bo = b0 + tx;
    if (mo < M && bo < Bsz) g_xT[mo * Bsz + bo] = tile[tx][ty];
}

// ---------------------------------------------------------------------------
// Kernel 4: main SpMM. One warp per output row n; lane holds float4 acc for
// b = 4*lane .. 4*lane+3. Integer weight sum accumulated in fp32 (exact up to
// fp32 addition of exact products * later scale); scale/bias applied once.
// ---------------------------------------------------------------------------
__global__ void __launch_bounds__(128)
spmm_kernel(const float* __restrict__ scales,
            const float* __restrict__ bias,
            float* __restrict__ y,
            int N, int Bsz)
{
    const int warp = threadIdx.x >> 5;
    const int lane = threadIdx.x & 31;
    const int r = blockIdx.x * 4 + warp;
    if (r >= N) return;

    const int s = g_rowptr[r];
    const int e = g_rowptr[r + 1];

    const float4* __restrict__ xT4 = (const float4*)g_xT;
    // each nnz: xT4[c * (Bsz/4) + lane]
    const int bq = Bsz >> 2;   // 32

    float4 acc = make_float4(0.f, 0.f, 0.f, 0.f);

    int k = s;
    // unroll by 4 for MLP against L2 latency
    for (; k + 4 <= e; k += 4) {
        uint32_t p0 = __ldg(&g_packed[k + 0]);
        uint32_t p1 = __ldg(&g_packed[k + 1]);
        uint32_t p2 = __ldg(&g_packed[k + 2]);
        uint32_t p3 = __ldg(&g_packed[k + 3]);
        float4 x0 = __ldg(&xT4[(p0 >> 8) * bq + lane]);
        float4 x1 = __ldg(&xT4[(p1 >> 8) * bq + lane]);
        float4 x2 = __ldg(&xT4[(p2 >> 8) * bq + lane]);
        float4 x3 = __ldg(&xT4[(p3 >> 8) * bq + lane]);
        float w0 = (float)(int)(p0 & 0xFFu) - 127.f;
        float w1 = (float)(int)(p1 & 0xFFu) - 127.f;
        float w2 = (float)(int)(p2 & 0xFFu) - 127.f;
        float w3 = (float)(int)(p3 & 0xFFu) - 127.f;
        acc.x += w0 * x0.x; acc.y += w0 * x0.y; acc.z += w0 * x0.z; acc.w += w0 * x0.w;
        acc.x += w1 * x1.x; acc.y += w1 * x1.y; acc.z += w1 * x1.z; acc.w += w1 * x1.w;
        acc.x += w2 * x2.x; acc.y += w2 * x2.y; acc.z += w2 * x2.z; acc.w += w2 * x2.w;
        acc.x += w3 * x3.x; acc.y += w3 * x3.y; acc.z += w3 * x3.z; acc.w += w3 * x3.w;
    }
    for (; k < e; ++k) {
        uint32_t p = __ldg(&g_packed[k]);
        float4 xv = __ldg(&xT4[(p >> 8) * bq + lane]);
        float w = (float)(int)(p & 0xFFu) - 127.f;
        acc.x += w * xv.x; acc.y += w * xv.y; acc.z += w * xv.z; acc.w += w * xv.w;
    }

    const float sc = scales[r];
    const float bi = bias[r];
    const int b0 = lane * 4;
    y[(b0 + 0) * N + r] = acc.x * sc + bi;
    y[(b0 + 1) * N + r] = acc.y * sc + bi;
    y[(b0 + 2) * N + r] = acc.z * sc + bi;
    y[(b0 + 3) * N + r] = acc.w * sc + bi;
}

// ---------------------------------------------------------------------------
// kernel_launch: inputs per metadata order:
//   0: x        [B*M]  f32
//   1: W_val_i  [NNZ]  i32
//   2: W_scales [N]    f32
//   3: row_ids  [NNZ]  i32
//   4: col_idx  [NNZ]  i32
//   5: bias     [N]    f32
// out: y [B*N] f32
// ---------------------------------------------------------------------------
extern "C" void kernel_launch(void* const* d_in, const int* in_sizes, int n_in,
                              void* d_out, int out_size)
{
    const float* x      = (const float*)d_in[0];
    const int*   wval   = (const int*)  d_in[1];
    const float* scales = (const float*)d_in[2];
    const int*   rowid  = (const int*)  d_in[3];
    const int*   colidx = (const int*)  d_in[4];
    const float* bias   = (const float*)d_in[5];
    float*       y      = (float*)d_out;

    const int NNZ = in_sizes[1];
    const int N   = in_sizes[5];
    const int B   = out_size / N;          // 128
    const int M   = in_sizes[0] / B;       // 4096

    // 1) pack
    pack_kernel<<<(NNZ + 255) / 256, 256>>>(wval, colidx, NNZ);

    // 2) rowptr
    rowptr_kernel<<<(N + 1 + 255) / 256, 256>>>(rowid, NNZ, N);

    // 3) transpose x -> xT
    {
        dim3 blk(32, 32);
        dim3 grd((M + 31) / 32, (B + 31) / 32);
        transpose_kernel<<<grd, blk>>>(x, B, M);
    }

    // 4) main spmm: one warp per row
    spmm_kernel<<<(N + 3) / 4, 128>>>(scales, bias, y, N, B);
}

// round 13
// speedup vs baseline: 1.2914x; 1.2914x over previous
#include <cuda_runtime.h>
#include <cuda_bf16.h>
#include <stdint.h>

#define MAX_N    4096
#define MAX_M    4096
#define MAX_B    128
#define MAX_NNZ  1638400

// __device__ global scratch (no allocations allowed)
__device__ uint32_t g_packed[MAX_NNZ];          // (col<<8) | (val+127)
__device__ int      g_rowptr[MAX_N + 1];
__device__ float    g_xT[MAX_M * MAX_B];        // xT[m*B + b], 2 MB -> L2 resident

// ---------------------------------------------------------------------------
// Fused prep kernel: block-range partitioned.
//   blocks [0, nT)            : transpose x[B,M] -> g_xT[M,B] (32x32 tiles)
//   blocks [nT, nT+nP)        : pack (col,val) -> g_packed
//   blocks [nT+nP, nT+nP+nR)  : rowptr binary search
// All three are independent; only spmm (next launch) depends on them.
// 1024 threads per block.
// ---------------------------------------------------------------------------
__global__ void __launch_bounds__(1024)
prep_kernel(const float* __restrict__ x,
            const int* __restrict__ wval,
            const int* __restrict__ col,
            const int* __restrict__ row_ids,
            int Bsz, int M, int nnz, int n,
            int nT, int nP)
{
    const int bid = blockIdx.x;
    const int tid = threadIdx.x;

    if (bid < nT) {
        // ---- transpose: one 32x32 tile per block ----
        __shared__ float tile[32][33];
        const int tilesM = M >> 5;              // tiles along M
        const int tm = bid % tilesM;
        const int tb = bid / tilesM;
        const int m0 = tm * 32;
        const int b0 = tb * 32;
        const int tx = tid & 31;
        const int ty = tid >> 5;

        int m = m0 + tx, b = b0 + ty;
        if (b < Bsz && m < M) tile[ty][tx] = x[b * M + m];
        __syncthreads();
        int mo = m0 + ty, bo = b0 + tx;
        if (mo < M && bo < Bsz) g_xT[mo * Bsz + bo] = tile[tx][ty];
    } else if (bid < nT + nP) {
        // ---- pack: 4096 elements per block ----
        const int base = (bid - nT) * 4096;
        #pragma unroll
        for (int i = 0; i < 4; ++i) {
            int k = base + i * 1024 + tid;
            if (k < nnz) {
                uint32_t c = (uint32_t)col[k];
                uint32_t v = (uint32_t)(wval[k] + 127);   // [-127,127] -> [0,254]
                g_packed[k] = (c << 8) | (v & 0xFFu);
            }
        }
    } else {
        // ---- rowptr: binary search on sorted row_ids ----
        const int r = (bid - nT - nP) * 1024 + tid;
        if (r <= n) {
            int lo = 0, hi = nnz;
            while (lo < hi) {
                int mid = (lo + hi) >> 1;
                if (row_ids[mid] < r) lo = mid + 1; else hi = mid;
            }
            g_rowptr[r] = lo;
        }
    }
}

// ---------------------------------------------------------------------------
// Main SpMM. TWO warps per output row (each half the nnz range),
// unroll-8 mainloop for deep MLP. lane holds float4 acc for b=4*lane..+3.
// Partials combined via smem. 256 thr/block -> 4 rows/block, 8192 warps.
// ---------------------------------------------------------------------------
__global__ void __launch_bounds__(256)
spmm_kernel(const float* __restrict__ scales,
            const float* __restrict__ bias,
            float* __restrict__ y,
            int N, int Bsz)
{
    __shared__ float4 red[4][32];    // partial acc from half==1 warps

    const int warp = threadIdx.x >> 5;
    const int lane = threadIdx.x & 31;
    const int rloc = warp >> 1;              // row within block (0..3)
    const int half = warp & 1;               // which half of nnz range
    const int r = blockIdx.x * 4 + rloc;
    const bool valid = (r < N);

    const float4* __restrict__ xT4 = (const float4*)g_xT;
    const int bq = Bsz >> 2;                 // 32

    float4 acc = make_float4(0.f, 0.f, 0.f, 0.f);

    if (valid) {
        const int s = g_rowptr[r];
        const int e = g_rowptr[r + 1];
        const int mid = s + ((e - s) >> 1);
        int k  = half ? mid : s;
        int ke = half ? e   : mid;

        // unroll-8 mainloop: 8 packed loads + 8 float4 x-loads in flight
        for (; k + 8 <= ke; k += 8) {
            uint32_t p[8];
            #pragma unroll
            for (int i = 0; i < 8; ++i) p[i] = __ldg(&g_packed[k + i]);

            float4 xv[8];
            #pragma unroll
            for (int i = 0; i < 8; ++i)
                xv[i] = __ldg(&xT4[(p[i] >> 8) * bq + lane]);

            #pragma unroll
            for (int i = 0; i < 8; ++i) {
                float w = (float)(int)(p[i] & 0xFFu) - 127.f;
                acc.x += w * xv[i].x;
                acc.y += w * xv[i].y;
                acc.z += w * xv[i].z;
                acc.w += w * xv[i].w;
            }
        }
        for (; k < ke; ++k) {
            uint32_t p = __ldg(&g_packed[k]);
            float4 xv = __ldg(&xT4[(p >> 8) * bq + lane]);
            float w = (float)(int)(p & 0xFFu) - 127.f;
            acc.x += w * xv.x; acc.y += w * xv.y; acc.z += w * xv.z; acc.w += w * xv.w;
        }
    }

    // combine the two half-warps' partials
    if (half == 1) red[rloc][lane] = acc;
    __syncthreads();

    if (valid && half == 0) {
        float4 o = red[rloc][lane];
        acc.x += o.x; acc.y += o.y; acc.z += o.z; acc.w += o.w;

        const float sc = scales[r];
        const float bi = bias[r];
        const int b0 = lane * 4;
        y[(b0 + 0) * N + r] = acc.x * sc + bi;
        y[(b0 + 1) * N + r] = acc.y * sc + bi;
        y[(b0 + 2) * N + r] = acc.z * sc + bi;
        y[(b0 + 3) * N + r] = acc.w * sc + bi;
    }
}

// ---------------------------------------------------------------------------
// kernel_launch: inputs per metadata order:
//   0: x [B*M] f32, 1: W_val_i [NNZ] i32, 2: W_scales [N] f32,
//   3: row_ids [NNZ] i32, 4: col_idx [NNZ] i32, 5: bias [N] f32
// out: y [B*N] f32
// ---------------------------------------------------------------------------
extern "C" void kernel_launch(void* const* d_in, const int* in_sizes, int n_in,
                              void* d_out, int out_size)
{
    const float* x      = (const float*)d_in[0];
    const int*   wval   = (const int*)  d_in[1];
    const float* scales = (const float*)d_in[2];
    const int*   rowid  = (const int*)  d_in[3];
    const int*   colidx = (const int*)  d_in[4];
    const float* bias   = (const float*)d_in[5];
    float*       y      = (float*)d_out;

    const int NNZ = in_sizes[1];
    const int N   = in_sizes[5];
    const int B   = out_size / N;          // 128
    const int M   = in_sizes[0] / B;       // 4096

    // fused prep: transpose + pack + rowptr in one launch
    const int nT = (M >> 5) * ((B + 31) >> 5);       // 128 * 4 = 512
    const int nP = (NNZ + 4095) / 4096;              // 400
    const int nR = (N + 1 + 1023) / 1024;            // 4
    prep_kernel<<<nT + nP + nR, 1024>>>(x, wval, colidx, rowid,
                                        B, M, NNZ, N, nT, nP);

    // main spmm: 2 warps per row
    spmm_kernel<<<(N + 3) / 4, 256>>>(scales, bias, y, N, B);
}